// round 2
// baseline (speedup 1.0000x reference)
#include <cuda_runtime.h>
#include <math.h>

// Problem constants
// B=256, LAT=20, HID=128, G=25000, BIN=25, C=7, GB=1000
// Output layout (concatenated f32):
//   mu      [256,25000]      @ 0
//   theta   [256,25000]      @ 6,400,000
//   pi_drop [256,25000]      @ 12,800,000
//   sample  [256,25000]      @ 19,200,000
//   pi      [256,25000,7]    @ 25,600,000   (total 70,400,000)

static __device__ float g_x1[256 * 128];
static __device__ float g_x2[256 * 128];
static __device__ float g_rho[256 * 1000 * 7];  // softmaxed rho, layout [b][bin][c]

// ---------------------------------------------------------------------------
// Threefry-2x32, 20 rounds, key = (0, 42)  (jax.random.key(42))
// ---------------------------------------------------------------------------
__device__ __forceinline__ void tf2x32(unsigned x0, unsigned x1,
                                       unsigned& o0, unsigned& o1) {
    const unsigned K0 = 0u;
    const unsigned K1 = 42u;
    const unsigned K2 = 0x1BD11BDAu ^ 0u ^ 42u;
    x0 += K0; x1 += K1;
#define TF_R(r) { x0 += x1; x1 = __funnelshift_l(x1, x1, r); x1 ^= x0; }
    TF_R(13) TF_R(15) TF_R(26) TF_R(6)
    x0 += K1; x1 += K2 + 1u;
    TF_R(17) TF_R(29) TF_R(16) TF_R(24)
    x0 += K2; x1 += K0 + 2u;
    TF_R(13) TF_R(15) TF_R(26) TF_R(6)
    x0 += K0; x1 += K1 + 3u;
    TF_R(17) TF_R(29) TF_R(16) TF_R(24)
    x0 += K1; x1 += K2 + 4u;
    TF_R(13) TF_R(15) TF_R(26) TF_R(6)
    x0 += K2; x1 += K0 + 5u;
#undef TF_R
    o0 = x0; o1 = x1;
}

// bits -> uniform [0,1) exactly as jax._src.random._uniform for f32
__device__ __forceinline__ float bits_to_uniform(unsigned bits) {
    return __uint_as_float((bits >> 9) | 0x3f800000u) - 1.0f;
}

// ---------------------------------------------------------------------------
// MLP layer 0: x1 = relu(bn(z @ w0 + b0))
// ---------------------------------------------------------------------------
__global__ void mlp0_kernel(const float* __restrict__ z, const float* __restrict__ w,
                            const float* __restrict__ bias, const float* __restrict__ gam,
                            const float* __restrict__ bet, const float* __restrict__ mean,
                            const float* __restrict__ var) {
    __shared__ float zr[20];
    int b = blockIdx.x, h = threadIdx.x;
    if (h < 20) zr[h] = z[b * 20 + h];
    __syncthreads();
    float acc = bias[h];
#pragma unroll
    for (int k = 0; k < 20; k++) acc = fmaf(zr[k], w[k * 128 + h], acc);
    acc = (acc - mean[h]) * rsqrtf(var[h] + 1e-3f) * gam[h] + bet[h];
    g_x1[b * 128 + h] = fmaxf(acc, 0.f);
}

// MLP layer 1: x2 = relu(bn(x1 @ w1 + b1))
__global__ void mlp1_kernel(const float* __restrict__ w, const float* __restrict__ bias,
                            const float* __restrict__ gam, const float* __restrict__ bet,
                            const float* __restrict__ mean, const float* __restrict__ var) {
    __shared__ float xr[128];
    int b = blockIdx.x, h = threadIdx.x;
    xr[h] = g_x1[b * 128 + h];
    __syncthreads();
    float acc = bias[h];
#pragma unroll
    for (int k = 0; k < 128; k++) acc = fmaf(xr[k], w[k * 128 + h], acc);
    acc = (acc - mean[h]) * rsqrtf(var[h] + 1e-3f) * gam[h] + bet[h];
    g_x2[b * 128 + h] = fmaxf(acc, 0.f);
}

// ---------------------------------------------------------------------------
// theta = exp(x2 @ wr + br), pi_drop = x2 @ wd + bd
// block: 256 threads = 256 g columns; 16 b-rows per block (grid.y = 16)
// ---------------------------------------------------------------------------
__global__ void big_gemm_kernel(const float* __restrict__ wr, const float* __restrict__ br,
                                const float* __restrict__ wd, const float* __restrict__ bd,
                                float* __restrict__ out) {
    __shared__ float xs[16 * 128];
    int tid = threadIdx.x;
    int b0r = blockIdx.y * 16;
    for (int i = tid; i < 16 * 128; i += 256) xs[i] = g_x2[b0r * 128 + i];
    __syncthreads();
    int g = blockIdx.x * 256 + tid;
    if (g >= 25000) return;
    float ar[16], ad[16];
    float brv = br[g], bdv = bd[g];
#pragma unroll
    for (int i = 0; i < 16; i++) { ar[i] = brv; ad[i] = bdv; }
#pragma unroll 4
    for (int k = 0; k < 128; k++) {
        float wrv = wr[k * 25000 + g];
        float wdv = wd[k * 25000 + g];
#pragma unroll
        for (int i = 0; i < 16; i++) {
            float xv = xs[i * 128 + k];
            ar[i] = fmaf(xv, wrv, ar[i]);
            ad[i] = fmaf(xv, wdv, ad[i]);
        }
    }
#pragma unroll
    for (int i = 0; i < 16; i++) {
        out[6400000 + (b0r + i) * 25000 + g] = expf(ar[i]);
        out[12800000 + (b0r + i) * 25000 + g] = ad[i];
    }
}

// ---------------------------------------------------------------------------
// rho heads: rho[c,b,o] = x2[b] . wrho[c,:,o] + brho[c,o], softmax over c,
// stored as g_rho[b][bin][c].
// thread = (b, 4 consecutive bins); blockDim (64,4), grid (4, 64)
// ---------------------------------------------------------------------------
__global__ void rho_kernel(const float* __restrict__ wrho, const float* __restrict__ brho) {
    __shared__ float xs[4 * 128];
    int tx = threadIdx.x, ty = threadIdx.y;
    int lt = ty * 64 + tx;
    int bbase = blockIdx.y * 4;
    for (int i = lt; i < 4 * 128; i += 256) xs[i] = g_x2[bbase * 128 + i];
    __syncthreads();
    int quad = blockIdx.x * 64 + tx;
    if (quad >= 250) return;
    int b = bbase + ty;
    float acc[7][4];
#pragma unroll
    for (int c = 0; c < 7; c++) {
        float4 bv = *(const float4*)&brho[c * 1000 + quad * 4];
        acc[c][0] = bv.x; acc[c][1] = bv.y; acc[c][2] = bv.z; acc[c][3] = bv.w;
    }
    for (int k = 0; k < 128; k++) {
        float xv = xs[ty * 128 + k];
#pragma unroll
        for (int c = 0; c < 7; c++) {
            float4 w = *(const float4*)&wrho[(c * 128 + k) * 1000 + quad * 4];
            acc[c][0] = fmaf(xv, w.x, acc[c][0]);
            acc[c][1] = fmaf(xv, w.y, acc[c][1]);
            acc[c][2] = fmaf(xv, w.z, acc[c][2]);
            acc[c][3] = fmaf(xv, w.w, acc[c][3]);
        }
    }
#pragma unroll
    for (int j = 0; j < 4; j++) {
        float m = acc[0][j];
#pragma unroll
        for (int c = 1; c < 7; c++) m = fmaxf(m, acc[c][j]);
        float e[7], s = 0.f;
#pragma unroll
        for (int c = 0; c < 7; c++) { e[c] = expf(acc[c][j] - m); s += e[c]; }
        float* dst = &g_rho[(b * 1000 + quad * 4 + j) * 7];
#pragma unroll
        for (int c = 0; c < 7; c++) dst[c] = e[c] / s;
    }
}

// ---------------------------------------------------------------------------
// Gumbel sampling + mu + pi output. PARTITIONABLE threefry:
//   bits[i] = out0 ^ out1 of threefry(key, (hi=0, lo=i)),  i = ((b*G)+g)*7+c
// argmax_c (pi+eps)/w, w = eps - log(u+eps), equals the reference argmax
// (log-monotone); ties summed like (y == max).
// pi staged through smem for coalesced stores.
// ---------------------------------------------------------------------------
__global__ void sample_kernel(const float* __restrict__ ws, const float* __restrict__ bs,
                              float* __restrict__ out) {
    __shared__ float sp[12 * 7];
    __shared__ float spo[256 * 7];
    int tid = threadIdx.x;
    int g0 = blockIdx.x * 256;
    int b = blockIdx.y;  // 0..255
    int nvalid = min(256, 25000 - g0);
    int bin0 = g0 / 25;
    int nbins = (g0 + nvalid - 1) / 25 - bin0 + 1;
    int npl = nbins * 7;
    for (int i = tid; i < npl; i += 256) {
        sp[i] = g_rho[(b * 1000 + bin0) * 7 + i];
    }
    __syncthreads();
    if (tid < nvalid) {
        int g = g0 + tid;
        int binl = g / 25 - bin0;
        const float* p = &sp[binl * 7];
        unsigned base = (unsigned)(b * 25000 + g) * 7u;
        float r[7];
        float mv = -1e30f;
#pragma unroll
        for (int c = 0; c < 7; c++) {
            unsigned o0, o1;
            tf2x32(0u, base + (unsigned)c, o0, o1);
            float u = bits_to_uniform(o0 ^ o1);
            float w = 1e-20f - logf(u + 1e-20f);
            float pc = p[c];
            spo[tid * 7 + c] = pc;
            r[c] = (pc + 1e-20f) / w;
            mv = fmaxf(mv, r[c]);
        }
        float s = 0.f;
#pragma unroll
        for (int c = 0; c < 7; c++) {
            if (r[c] == mv) s += (float)c;
        }
        float wsg = ws[g], bsg = bs[g];
        out[b * 25000 + g] = 1.f / (1.f + expf(-(s * wsg + bsg)));
        out[19200000 + b * 25000 + g] = s;
    }
    __syncthreads();
    int tot = nvalid * 7;
    float* pib = out + 25600000u + (unsigned)(b * 25000 + g0) * 7u;
    for (int i = tid; i < tot; i += 256) {
        pib[i] = spo[i];
    }
}

// ---------------------------------------------------------------------------
extern "C" void kernel_launch(void* const* d_in, const int* in_sizes, int n_in,
                              void* d_out, int out_size) {
    const float* z    = (const float*)d_in[0];
    const float* w0   = (const float*)d_in[1];
    const float* b0   = (const float*)d_in[2];
    const float* g0   = (const float*)d_in[3];
    const float* be0  = (const float*)d_in[4];
    const float* m0   = (const float*)d_in[5];
    const float* v0   = (const float*)d_in[6];
    const float* w1   = (const float*)d_in[7];
    const float* b1   = (const float*)d_in[8];
    const float* g1   = (const float*)d_in[9];
    const float* be1  = (const float*)d_in[10];
    const float* m1   = (const float*)d_in[11];
    const float* v1   = (const float*)d_in[12];
    const float* wr   = (const float*)d_in[13];
    const float* br   = (const float*)d_in[14];
    const float* wd   = (const float*)d_in[15];
    const float* bd   = (const float*)d_in[16];
    const float* wrho = (const float*)d_in[17];
    const float* brho = (const float*)d_in[18];
    const float* wsc  = (const float*)d_in[19];
    const float* bsc  = (const float*)d_in[20];
    float* out = (float*)d_out;

    mlp0_kernel<<<256, 128>>>(z, w0, b0, g0, be0, m0, v0);
    mlp1_kernel<<<256, 128>>>(w1, b1, g1, be1, m1, v1);
    big_gemm_kernel<<<dim3(98, 16), 256>>>(wr, br, wd, bd, out);
    rho_kernel<<<dim3(4, 64), dim3(64, 4)>>>(wrho, brho);
    sample_kernel<<<dim3(98, 256), 256>>>(wsc, bsc, out);
}

// round 3
// speedup vs baseline: 1.3259x; 1.3259x over previous
#include <cuda_runtime.h>
#include <math.h>

// Problem constants
// B=256, LAT=20, HID=128, G=25000, BIN=25, C=7, GB=1000
// Output layout (concatenated f32):
//   mu      [256,25000]      @ 0
//   theta   [256,25000]      @ 6,400,000
//   pi_drop [256,25000]      @ 12,800,000
//   sample  [256,25000]      @ 19,200,000
//   pi      [256,25000,7]    @ 25,600,000   (total 70,400,000)

static __device__ float g_x2[256 * 128];
static __device__ float g_logits[256 * 7000];     // rho logits [b][c*1000+o]
static __device__ float g_rho[256 * 1000 * 7];    // softmaxed rho, layout [b][bin][c]

// ---------------------------------------------------------------------------
// packed f32x2 helpers (Blackwell FFMA2 path)
// ---------------------------------------------------------------------------
__device__ __forceinline__ unsigned long long packf2(float lo, float hi) {
    unsigned long long r;
    asm("mov.b64 %0, {%1, %2};" : "=l"(r) : "f"(lo), "f"(hi));
    return r;
}
__device__ __forceinline__ float2 unpackf2(unsigned long long v) {
    float lo, hi;
    asm("mov.b64 {%0, %1}, %2;" : "=f"(lo), "=f"(hi) : "l"(v));
    return make_float2(lo, hi);
}
__device__ __forceinline__ void ffma2(unsigned long long& d, unsigned long long a,
                                      unsigned long long b) {
    asm("fma.rn.f32x2 %0, %1, %2, %0;" : "+l"(d) : "l"(a), "l"(b));
}

// ---------------------------------------------------------------------------
// Threefry-2x32, 20 rounds, key = (0, 42), partitionable mode
// ---------------------------------------------------------------------------
__device__ __forceinline__ void tf2x32(unsigned x0, unsigned x1,
                                       unsigned& o0, unsigned& o1) {
    const unsigned K0 = 0u;
    const unsigned K1 = 42u;
    const unsigned K2 = 0x1BD11BDAu ^ 0u ^ 42u;
    x0 += K0; x1 += K1;
#define TF_R(r) { x0 += x1; x1 = __funnelshift_l(x1, x1, r); x1 ^= x0; }
    TF_R(13) TF_R(15) TF_R(26) TF_R(6)
    x0 += K1; x1 += K2 + 1u;
    TF_R(17) TF_R(29) TF_R(16) TF_R(24)
    x0 += K2; x1 += K0 + 2u;
    TF_R(13) TF_R(15) TF_R(26) TF_R(6)
    x0 += K0; x1 += K1 + 3u;
    TF_R(17) TF_R(29) TF_R(16) TF_R(24)
    x0 += K1; x1 += K2 + 4u;
    TF_R(13) TF_R(15) TF_R(26) TF_R(6)
    x0 += K2; x1 += K0 + 5u;
#undef TF_R
    o0 = x0; o1 = x1;
}

__device__ __forceinline__ float bits_to_uniform(unsigned bits) {
    return __uint_as_float((bits >> 9) | 0x3f800000u) - 1.0f;
}

// ---------------------------------------------------------------------------
// Fused MLP: x2 = relu(bn(relu(bn(z@w0+b0)) @ w1 + b1))   (row-independent)
// ---------------------------------------------------------------------------
__global__ void mlp_kernel(const float* __restrict__ z,
                           const float* __restrict__ w0, const float* __restrict__ b0,
                           const float* __restrict__ g0, const float* __restrict__ be0,
                           const float* __restrict__ m0, const float* __restrict__ v0,
                           const float* __restrict__ w1, const float* __restrict__ b1,
                           const float* __restrict__ g1, const float* __restrict__ be1,
                           const float* __restrict__ m1, const float* __restrict__ v1) {
    __shared__ float zr[20];
    __shared__ float xr[128];
    int b = blockIdx.x, h = threadIdx.x;
    if (h < 20) zr[h] = z[b * 20 + h];
    __syncthreads();
    float acc = b0[h];
#pragma unroll
    for (int k = 0; k < 20; k++) acc = fmaf(zr[k], w0[k * 128 + h], acc);
    acc = (acc - m0[h]) * rsqrtf(v0[h] + 1e-3f) * g0[h] + be0[h];
    xr[h] = fmaxf(acc, 0.f);
    __syncthreads();
    float acc2 = b1[h];
#pragma unroll 8
    for (int k = 0; k < 128; k++) acc2 = fmaf(xr[k], w1[k * 128 + h], acc2);
    acc2 = (acc2 - m1[h]) * rsqrtf(v1[h] + 1e-3f) * g1[h] + be1[h];
    g_x2[b * 128 + h] = fmaxf(acc2, 0.f);
}

// ---------------------------------------------------------------------------
// theta = exp(x2 @ wr + br), pi_drop = x2 @ wd + bd
// b-tile = 32 (16 packed f32x2 accumulator pairs per matrix), grid (98, 8)
// ---------------------------------------------------------------------------
__global__ void __launch_bounds__(256, 2)
big_gemm_kernel(const float* __restrict__ wr, const float* __restrict__ br,
                const float* __restrict__ wd, const float* __restrict__ bd,
                float* __restrict__ out) {
    __shared__ unsigned long long xsp[128 * 16];  // [k][i2] = (x2[b0+2i2][k], x2[b0+2i2+1][k])
    int tid = threadIdx.x;
    int b0r = blockIdx.y * 32;
    for (int i = tid; i < 128 * 16; i += 256) {
        int k = i >> 4, i2 = i & 15;
        float lo = g_x2[(b0r + 2 * i2) * 128 + k];
        float hi = g_x2[(b0r + 2 * i2 + 1) * 128 + k];
        xsp[i] = packf2(lo, hi);
    }
    __syncthreads();
    int g = blockIdx.x * 256 + tid;
    if (g >= 25000) return;
    unsigned long long ar[16], ad[16];
    {
        float brv = br[g], bdv = bd[g];
        unsigned long long br2 = packf2(brv, brv), bd2 = packf2(bdv, bdv);
#pragma unroll
        for (int i = 0; i < 16; i++) { ar[i] = br2; ad[i] = bd2; }
    }
#pragma unroll 2
    for (int k = 0; k < 128; k++) {
        float wrv = wr[k * 25000 + g];
        float wdv = wd[k * 25000 + g];
        unsigned long long wr2 = packf2(wrv, wrv);
        unsigned long long wd2 = packf2(wdv, wdv);
#pragma unroll
        for (int i = 0; i < 16; i++) {
            unsigned long long xv = xsp[k * 16 + i];
            ffma2(ar[i], xv, wr2);
            ffma2(ad[i], xv, wd2);
        }
    }
#pragma unroll
    for (int i = 0; i < 16; i++) {
        float2 tr = unpackf2(ar[i]);
        float2 td = unpackf2(ad[i]);
        out[6400000 + (b0r + 2 * i) * 25000 + g] = expf(tr.x);
        out[6400000 + (b0r + 2 * i + 1) * 25000 + g] = expf(tr.y);
        out[12800000 + (b0r + 2 * i) * 25000 + g] = td.x;
        out[12800000 + (b0r + 2 * i + 1) * 25000 + g] = td.y;
    }
}

// ---------------------------------------------------------------------------
// rho GEMM: logits[b][j] = x2[b] . wrho[c,:,o] + brho[c,o],  j = c*1000+o
// thread = column j, b-tile = 16 (8 f32x2 pairs), grid (28, 16)
// ---------------------------------------------------------------------------
__global__ void __launch_bounds__(256, 4)
rho_gemm_kernel(const float* __restrict__ wrho, const float* __restrict__ brho) {
    __shared__ unsigned long long xsp[128 * 8];
    int tid = threadIdx.x;
    int b0r = blockIdx.y * 16;
    for (int i = tid; i < 128 * 8; i += 256) {
        int k = i >> 3, i2 = i & 7;
        float lo = g_x2[(b0r + 2 * i2) * 128 + k];
        float hi = g_x2[(b0r + 2 * i2 + 1) * 128 + k];
        xsp[i] = packf2(lo, hi);
    }
    __syncthreads();
    int j = blockIdx.x * 256 + tid;
    if (j >= 7000) return;
    int c = j / 1000;
    int o = j - c * 1000;
    const float* wb = wrho + c * 128000 + o;
    unsigned long long acc[8];
    {
        float bv = brho[c * 1000 + o];
        unsigned long long b2 = packf2(bv, bv);
#pragma unroll
        for (int i = 0; i < 8; i++) acc[i] = b2;
    }
#pragma unroll 4
    for (int k = 0; k < 128; k++) {
        float wv = wb[k * 1000];
        unsigned long long w2 = packf2(wv, wv);
#pragma unroll
        for (int i = 0; i < 8; i++) ffma2(acc[i], xsp[k * 8 + i], w2);
    }
#pragma unroll
    for (int i = 0; i < 8; i++) {
        float2 t = unpackf2(acc[i]);
        g_logits[(b0r + 2 * i) * 7000 + j] = t.x;
        g_logits[(b0r + 2 * i + 1) * 7000 + j] = t.y;
    }
}

// ---------------------------------------------------------------------------
// rho softmax over c: g_rho[b][o][c] = softmax_c(logits[b][c*1000+o])
// block handles 256 o's for one b; smem-staged coalesced writes. grid (4, 256)
// ---------------------------------------------------------------------------
__global__ void rho_softmax_kernel() {
    __shared__ float sm[256 * 7];
    int tid = threadIdx.x;
    int o0 = blockIdx.x * 256;
    int b = blockIdx.y;
    int nvalid = min(256, 1000 - o0);
    if (tid < nvalid) {
        int o = o0 + tid;
        float v[7];
        float mx = -1e30f;
#pragma unroll
        for (int c = 0; c < 7; c++) {
            v[c] = g_logits[b * 7000 + c * 1000 + o];
            mx = fmaxf(mx, v[c]);
        }
        float s = 0.f;
#pragma unroll
        for (int c = 0; c < 7; c++) { v[c] = expf(v[c] - mx); s += v[c]; }
        float inv = 1.f / s;
#pragma unroll
        for (int c = 0; c < 7; c++) sm[tid * 7 + c] = v[c] * inv;
    }
    __syncthreads();
    int tot = nvalid * 7;
    float* dst = &g_rho[(b * 1000 + o0) * 7];
    for (int i = tid; i < tot; i += 256) dst[i] = sm[i];
}

// ---------------------------------------------------------------------------
// Gumbel sampling + mu + pi output. PARTITIONABLE threefry:
//   bits[i] = out0 ^ out1 of threefry(key, (hi=0, lo=i)),  i = ((b*G)+g)*7+c
// argmax_c (pi+eps)/w, w = eps - log(u+eps), equals the reference argmax
// (log-monotone); ties summed like (y == max).
// ---------------------------------------------------------------------------
__global__ void sample_kernel(const float* __restrict__ ws, const float* __restrict__ bs,
                              float* __restrict__ out) {
    __shared__ float sp[12 * 7];
    __shared__ float spo[256 * 7];
    int tid = threadIdx.x;
    int g0 = blockIdx.x * 256;
    int b = blockIdx.y;  // 0..255
    int nvalid = min(256, 25000 - g0);
    int bin0 = g0 / 25;
    int nbins = (g0 + nvalid - 1) / 25 - bin0 + 1;
    int npl = nbins * 7;
    for (int i = tid; i < npl; i += 256) {
        sp[i] = g_rho[(b * 1000 + bin0) * 7 + i];
    }
    __syncthreads();
    if (tid < nvalid) {
        int g = g0 + tid;
        int binl = g / 25 - bin0;
        const float* p = &sp[binl * 7];
        unsigned base = (unsigned)(b * 25000 + g) * 7u;
        float r[7];
        float mv = -1e30f;
#pragma unroll
        for (int c = 0; c < 7; c++) {
            unsigned o0, o1;
            tf2x32(0u, base + (unsigned)c, o0, o1);
            float u = bits_to_uniform(o0 ^ o1);
            float w = 1e-20f - logf(u + 1e-20f);
            float pc = p[c];
            spo[tid * 7 + c] = pc;
            r[c] = (pc + 1e-20f) / w;
            mv = fmaxf(mv, r[c]);
        }
        float s = 0.f;
#pragma unroll
        for (int c = 0; c < 7; c++) {
            if (r[c] == mv) s += (float)c;
        }
        float wsg = ws[g], bsg = bs[g];
        out[b * 25000 + g] = 1.f / (1.f + expf(-(s * wsg + bsg)));
        out[19200000 + b * 25000 + g] = s;
    }
    __syncthreads();
    int tot = nvalid * 7;
    float* pib = out + 25600000u + (unsigned)(b * 25000 + g0) * 7u;
    for (int i = tid; i < tot; i += 256) {
        pib[i] = spo[i];
    }
}

// ---------------------------------------------------------------------------
extern "C" void kernel_launch(void* const* d_in, const int* in_sizes, int n_in,
                              void* d_out, int out_size) {
    const float* z    = (const float*)d_in[0];
    const float* w0   = (const float*)d_in[1];
    const float* b0   = (const float*)d_in[2];
    const float* g0   = (const float*)d_in[3];
    const float* be0  = (const float*)d_in[4];
    const float* m0   = (const float*)d_in[5];
    const float* v0   = (const float*)d_in[6];
    const float* w1   = (const float*)d_in[7];
    const float* b1   = (const float*)d_in[8];
    const float* g1   = (const float*)d_in[9];
    const float* be1  = (const float*)d_in[10];
    const float* m1   = (const float*)d_in[11];
    const float* v1   = (const float*)d_in[12];
    const float* wr   = (const float*)d_in[13];
    const float* br   = (const float*)d_in[14];
    const float* wd   = (const float*)d_in[15];
    const float* bd   = (const float*)d_in[16];
    const float* wrho = (const float*)d_in[17];
    const float* brho = (const float*)d_in[18];
    const float* wsc  = (const float*)d_in[19];
    const float* bsc  = (const float*)d_in[20];
    float* out = (float*)d_out;

    mlp_kernel<<<256, 128>>>(z, w0, b0, g0, be0, m0, v0, w1, b1, g1, be1, m1, v1);
    big_gemm_kernel<<<dim3(98, 8), 256>>>(wr, br, wd, bd, out);
    rho_gemm_kernel<<<dim3(28, 16), 256>>>(wrho, brho);
    rho_softmax_kernel<<<dim3(4, 256), 256>>>();
    sample_kernel<<<dim3(98, 256), 256>>>(wsc, bsc, out);
}